// round 13
// baseline (speedup 1.0000x reference)
#include <cuda_runtime.h>
#include <math.h>

// Problem constants
#define Bn 2
#define Nn 1024
#define Dn 1024
#define Hn 16
#define HDn 64
#define BHn 32
#define NBn 16

typedef float2 f2;

// ---------------- device scratch (all fp32) ----------------
__device__ float g_Ww[Dn*Dn];                   // Ww1@Ww2
__device__ float g_bf[8*2048*32];               // K-split partials of x@[Wb|Wf]
__device__ float g_beta[BHn*Nn];
__device__ float g_Fc[BHn*Nn];
__device__ float g_q[BHn*Nn*HDn];               // head-major
__device__ float g_k[BHn*Nn*HDn];
__device__ float g_v[BHn*Nn*HDn];
__device__ float g_w[BHn*Nn*HDn];               // l2-normalized
__device__ float g_Tinv[BHn*NBn*4096];
__device__ float g_L[(size_t)BHn*NBn*NBn*4096]; // NEGATED L, blocked 64x64
__device__ float g_C[(size_t)BHn*Nn*Nn];
__device__ float g_G[(size_t)BHn*Nn*Nn];        // NEGATED G, dense
__device__ float g_S[(size_t)BHn*Nn*Nn];        // logits -> P in place
__device__ float g_o[Bn*Nn*Dn];

// ---------------- tf32 split + mma ----------------
// 2-instruction split: hi = rna(x), lo = x - hi passed raw (R12-verified).
__device__ __forceinline__ f2 splt(float x) {
    unsigned h;
    asm("cvt.rna.tf32.f32 %0, %1;" : "=r"(h) : "f"(x));
    float hf = __uint_as_float(h);
    return make_float2(hf, x - hf);
}

__device__ __forceinline__ void mma_raw(float c[4], float a0, float a1, float a2, float a3,
                                        float b0, float b1) {
    unsigned A0 = __float_as_uint(a0), A1 = __float_as_uint(a1);
    unsigned A2 = __float_as_uint(a2), A3 = __float_as_uint(a3);
    unsigned B0 = __float_as_uint(b0), B1 = __float_as_uint(b1);
    asm volatile(
        "mma.sync.aligned.m16n8k8.row.col.f32.tf32.tf32.f32 "
        "{%0,%1,%2,%3}, {%4,%5,%6,%7}, {%8,%9}, {%0,%1,%2,%3};"
        : "+f"(c[0]), "+f"(c[1]), "+f"(c[2]), "+f"(c[3])
        : "r"(A0), "r"(A1), "r"(A2), "r"(A3), "r"(B0), "r"(B1));
}

// Warp computes 16x32 region of a 64x64x64 tile product.
// DUAL accumulators: accM gets hi*hi, accC gets hi*lo + lo*hi (summed at epilogue).
// Doubles independent mma chains (4 -> 8) vs single-acc version.
template<bool BT>
__device__ __forceinline__ void wtile32(float accM[4][4], float accC[4][4],
                                        const float (*A)[68], const float (*B)[68],
                                        int m0, int n0) {
    int lane = threadIdx.x & 31;
    int g = lane >> 2, tig = lane & 3;
#pragma unroll
    for (int k0 = 0; k0 < 64; k0 += 8) {
        f2 A0 = splt(A[m0 + g][k0 + tig]);
        f2 A1 = splt(A[m0 + g + 8][k0 + tig]);
        f2 A2 = splt(A[m0 + g][k0 + tig + 4]);
        f2 A3 = splt(A[m0 + g + 8][k0 + tig + 4]);
#pragma unroll
        for (int nf = 0; nf < 4; nf++) {
            int nn = n0 + nf * 8 + g;
            f2 B0 = splt(BT ? B[nn][k0 + tig]     : B[k0 + tig][nn]);
            f2 B1 = splt(BT ? B[nn][k0 + tig + 4] : B[k0 + tig + 4][nn]);
            mma_raw(accM[nf], A0.x, A1.x, A2.x, A3.x, B0.x, B1.x);
            mma_raw(accC[nf], A0.x, A1.x, A2.x, A3.x, B0.y, B1.y);
            mma_raw(accC[nf], A0.y, A1.y, A2.y, A3.y, B0.x, B1.x);
        }
    }
}

// ---------------- cp.async helpers ----------------
__device__ __forceinline__ void cp16(void* sdst, const void* gsrc) {
    unsigned s = (unsigned)__cvta_generic_to_shared(sdst);
    asm volatile("cp.async.ca.shared.global [%0], [%1], 16;" :: "r"(s), "l"(gsrc));
}
__device__ __forceinline__ void cp16cg(void* sdst, const void* gsrc) {
    unsigned s = (unsigned)__cvta_generic_to_shared(sdst);
    asm volatile("cp.async.cg.shared.global [%0], [%1], 16;" :: "r"(s), "l"(gsrc));
}
__device__ __forceinline__ void cp_commit() { asm volatile("cp.async.commit_group;"); }
template<int N> __device__ __forceinline__ void cp_wait() {
    asm volatile("cp.async.wait_group %0;" :: "n"(N));
}

// Async-copy a 64x64 fp32 tile (row stride in floats, multiple of 4) into padded smem.
template<bool CG>
__device__ __forceinline__ void cpa_tile(float (*sm)[68], const float* __restrict__ g, int stride) {
    int t = threadIdx.x;
    int r = t >> 2;
    int c4 = (t & 3) << 4;
    const float* gp = g + (size_t)r * stride + c4;
#pragma unroll
    for (int q = 0; q < 4; q++) {
        if (CG) cp16cg(&sm[r][c4 + 4*q], gp + 4*q);
        else    cp16  (&sm[r][c4 + 4*q], gp + 4*q);
    }
}

#define EPI_COORDS \
    int lane = threadIdx.x & 31, wrp = threadIdx.x >> 5; \
    int g = lane >> 2, tig = lane & 3; \
    int wm = (wrp & 3) * 16, wn = (wrp >> 2) * 32; \
    (void)g; (void)tig; (void)wm; (void)wn;

#define STAGE_F (64 * 68)
#define SM_PIPE (4 * STAGE_F * (int)sizeof(float))   // 69632 B
#define SM_ONE  (2 * STAGE_F * (int)sizeof(float))
#define SM_TINV ((STAGE_F + 2 * 64 * 65) * (int)sizeof(float))

// ---------------- scalar GEMM (Ww only) ----------------
__global__ void gemm_kernel(const float* __restrict__ A, const float* __restrict__ Bm,
                            float* __restrict__ C, int M, int Ncols, int K) {
    __shared__ float As[16][65];
    __shared__ float Bs[16][65];
    int m0 = blockIdx.y * 64, n0 = blockIdx.x * 64;
    int tid = threadIdx.x;
    int ty = (tid >> 4) << 2, tx = (tid & 15) << 2;
    int lrA = tid >> 2, lcA = (tid & 3) << 2;
    int krB = tid >> 4, ncB = (tid & 15) << 2;
    float acc[4][4] = {};
    for (int k0 = 0; k0 < K; k0 += 16) {
        float4 va = *(const float4*)(A + (size_t)(m0 + lrA) * K + k0 + lcA);
        As[lcA + 0][lrA] = va.x;
        As[lcA + 1][lrA] = va.y;
        As[lcA + 2][lrA] = va.z;
        As[lcA + 3][lrA] = va.w;
#pragma unroll
        for (int q = 0; q < 4; q++)
            Bs[krB][ncB + q] = Bm[(size_t)(k0 + krB) * Ncols + n0 + ncB + q];
        __syncthreads();
#pragma unroll
        for (int kk = 0; kk < 16; kk++) {
            float a[4], b[4];
#pragma unroll
            for (int i = 0; i < 4; i++) a[i] = As[kk][ty + i];
#pragma unroll
            for (int j = 0; j < 4; j++) b[j] = Bs[kk][tx + j];
#pragma unroll
            for (int i = 0; i < 4; i++)
#pragma unroll
                for (int j = 0; j < 4; j++)
                    acc[i][j] += a[i] * b[j];
        }
        __syncthreads();
    }
#pragma unroll
    for (int i = 0; i < 4; i++)
#pragma unroll
        for (int j = 0; j < 4; j++)
            C[(size_t)(m0 + ty + i) * Ncols + n0 + tx + j] = acc[i][j];
}

// ---------------- K-split partials of x @ [Wb|Wf] ----------------
__global__ void bf_kernel(const float* __restrict__ x, const float* __restrict__ Wb,
                          const float* __restrict__ Wf) {
    extern __shared__ float dsm[];
    float* xs = dsm;              // [64][128]
    float* Bs = dsm + 64 * 128;   // [128][32]
    int m0 = blockIdx.x * 64;
    int kz = blockIdx.y;
    int tid = threadIdx.x;
    for (int idx = tid; idx < 128 * 32; idx += 256) {
        int k = idx >> 5, c = idx & 31;
        int kg = kz * 128 + k;
        Bs[idx] = (c < 16) ? Wb[kg * 16 + c] : Wf[kg * 16 + (c - 16)];
    }
    for (int idx = tid * 4; idx < 64 * 128; idx += 1024) {
        int r = idx >> 7, k = idx & 127;
        *(float4*)&xs[idx] = *(const float4*)(x + (size_t)(m0 + r) * Dn + kz * 128 + k);
    }
    __syncthreads();
    int tx = tid & 31, ry = tid >> 5;
    float acc[8] = {};
    for (int k = 0; k < 128; k++) {
        float bv = Bs[k * 32 + tx];
#pragma unroll
        for (int s = 0; s < 8; s++)
            acc[s] += xs[(ry + 8 * s) * 128 + k] * bv;
    }
#pragma unroll
    for (int s = 0; s < 8; s++)
        g_bf[((size_t)kz * 2048 + m0 + ry + 8 * s) * 32 + tx] = acc[s];
}

// ---------------- gates ----------------
__global__ void gate_kernel(const float* __restrict__ delta) {
    int bh = blockIdx.x, tid = threadIdx.x;
    int b = bh >> 4, h = bh & 15;
    __shared__ float part[256];
    float v[4];
#pragma unroll
    for (int u = 0; u < 4; u++) {
        int n = tid * 4 + u;
        int row = (b << 10) + n;
        float bbv = 0.f, ffv = 0.f;
#pragma unroll
        for (int z = 0; z < 8; z++) {
            bbv += g_bf[((size_t)z * 2048 + row) * 32 + h];
            ffv += g_bf[((size_t)z * 2048 + row) * 32 + 16 + h];
        }
        g_beta[bh * Nn + n] = 2.f / (1.f + expf(-bbv));
        float z2 = ffv + delta[h];
        v[u] = fminf(z2, 0.f) - log1pf(expf(-fabsf(z2)));
    }
    v[1] += v[0]; v[2] += v[1]; v[3] += v[2];
    part[tid] = v[3];
    __syncthreads();
    if (tid == 0) {
        float run = 0.f;
        for (int t = 0; t < 256; t++) { float tmp = part[t]; part[t] = run; run += tmp; }
    }
    __syncthreads();
    float off = part[tid];
#pragma unroll
    for (int u = 0; u < 4; u++)
        g_Fc[bh * Nn + tid * 4 + u] = off + v[u];
}

// ---------------- fused projections q/k/v/w (pipelined, single-sync rounds) ----------------
__global__ void proj_kernel(const float* __restrict__ x, const float* __restrict__ Wq,
                            const float* __restrict__ Wk, const float* __restrict__ Wv) {
    int h = blockIdx.x, mt = blockIdx.y, z = blockIdx.z;
    const float* W = (z == 0) ? Wq : (z == 1) ? Wk : (z == 2) ? Wv : g_Ww;
    extern __shared__ float smem[];
    float (*stA)[64][68] = (float(*)[64][68])smem;
    float (*stB)[64][68] = (float(*)[64][68])(smem + 2 * STAGE_F);
    int m0 = mt * 64, n0 = h * 64;
    EPI_COORDS;
    float accM[4][4] = {}, accC[4][4] = {};
    cpa_tile<false>(stA[0], x + (size_t)m0 * Dn, Dn);
    cpa_tile<false>(stB[0], W + n0, Dn);
    cp_commit();
    for (int r = 0; r < 16; r++) {
        cp_wait<0>();
        __syncthreads();
        if (r + 1 < 16) {
            cpa_tile<false>(stA[(r + 1) & 1], x + (size_t)m0 * Dn + (r + 1) * 64, Dn);
            cpa_tile<false>(stB[(r + 1) & 1], W + (size_t)((r + 1) * 64) * Dn + n0, Dn);
            cp_commit();
        }
        wtile32<false>(accM, accC, stA[r & 1], stB[r & 1], wm, wn);
    }
    int b = m0 >> 10;
    int nbase = m0 & 1023;
    float* dst = ((z == 0) ? g_q : (z == 1) ? g_k : (z == 2) ? g_v : g_w)
                 + ((size_t)(b * Hn + h) * Nn) * HDn;
    if (z < 3) {
#pragma unroll
        for (int nf = 0; nf < 4; nf++) {
            int c = wn + nf * 8 + 2 * tig;
            int r0 = wm + g, r1 = r0 + 8;
            dst[(size_t)(nbase + r0) * HDn + c]     = accM[nf][0] + accC[nf][0];
            dst[(size_t)(nbase + r0) * HDn + c + 1] = accM[nf][1] + accC[nf][1];
            dst[(size_t)(nbase + r1) * HDn + c]     = accM[nf][2] + accC[nf][2];
            dst[(size_t)(nbase + r1) * HDn + c + 1] = accM[nf][3] + accC[nf][3];
        }
    } else {
        float (*sT)[68] = stA[0];
        __shared__ float rnorm[64];
        __syncthreads();   // all warps past final wtile before reusing stA[0]
#pragma unroll
        for (int nf = 0; nf < 4; nf++) {
            int c = wn + nf * 8 + 2 * tig;
            int r0 = wm + g, r1 = r0 + 8;
            sT[r0][c]     = accM[nf][0] + accC[nf][0];
            sT[r0][c + 1] = accM[nf][1] + accC[nf][1];
            sT[r1][c]     = accM[nf][2] + accC[nf][2];
            sT[r1][c + 1] = accM[nf][3] + accC[nf][3];
        }
        __syncthreads();
        if (threadIdx.x < 64) {
            float s = 1e-6f;
            for (int c = 0; c < 64; c++) { float w = sT[threadIdx.x][c]; s += w * w; }
            rnorm[threadIdx.x] = rsqrtf(s);
        }
        __syncthreads();
#pragma unroll
        for (int nf = 0; nf < 4; nf++) {
            int c = wn + nf * 8 + 2 * tig;
            int r0 = wm + g, r1 = r0 + 8;
            dst[(size_t)(nbase + r0) * HDn + c]     = sT[r0][c]     * rnorm[r0];
            dst[(size_t)(nbase + r0) * HDn + c + 1] = sT[r0][c + 1] * rnorm[r0];
            dst[(size_t)(nbase + r1) * HDn + c]     = sT[r1][c]     * rnorm[r1];
            dst[(size_t)(nbase + r1) * HDn + c + 1] = sT[r1][c + 1] * rnorm[r1];
        }
    }
}

// ---------------- L blocks (NEGATED) ----------------
__global__ void l_kernel() {
    int bx = blockIdx.x;
    int i = bx >> 4, r = bx & 15;
    if (r >= i) return;
    int bh = blockIdx.y;
    extern __shared__ float smem[];
    float (*sA)[68] = (float(*)[68])smem;
    float (*sB)[68] = (float(*)[68])(smem + STAGE_F);
    cpa_tile<false>(sA, g_w + ((size_t)bh * Nn + i * 64) * HDn, HDn);
    cpa_tile<false>(sB, g_w + ((size_t)bh * Nn + r * 64) * HDn, HDn);
    cp_commit(); cp_wait<0>();
    __syncthreads();
    EPI_COORDS;
    float accM[4][4] = {}, accC[4][4] = {};
    wtile32<true>(accM, accC, sA, sB, wm, wn);
    float* out = g_L + (((size_t)bh * NBn + i) * NBn + r) * 4096;
    const float* bet = g_beta + bh * Nn + r * 64;
#pragma unroll
    for (int nf = 0; nf < 4; nf++) {
        int c = wn + nf * 8 + 2 * tig;
        int r0 = wm + g, r1 = r0 + 8;
        out[r0 * 64 + c]     = -(accM[nf][0] + accC[nf][0]) * bet[c];
        out[r0 * 64 + c + 1] = -(accM[nf][1] + accC[nf][1]) * bet[c + 1];
        out[r1 * 64 + c]     = -(accM[nf][2] + accC[nf][2]) * bet[c];
        out[r1 * 64 + c + 1] = -(accM[nf][3] + accC[nf][3]) * bet[c + 1];
    }
}

// ---------------- Tinv = (I + L_ii)^-1 ----------------
__global__ void tinv_kernel() {
    int i = blockIdx.x, bh = blockIdx.y, tid = threadIdx.x;
    extern __shared__ float smem[];
    float (*sW)[68] = (float(*)[68])smem;
    float (*Ml)[65] = (float(*)[65])(smem + STAGE_F);
    float (*X)[65]  = (float(*)[65])(smem + STAGE_F + 64 * 65);
    cpa_tile<false>(sW, g_w + ((size_t)bh * Nn + i * 64) * HDn, HDn);
    cp_commit(); cp_wait<0>();
    __syncthreads();
    EPI_COORDS;
    float accM[4][4] = {}, accC[4][4] = {};
    wtile32<true>(accM, accC, sW, sW, wm, wn);
    const float* bet = g_beta + bh * Nn + i * 64;
#pragma unroll
    for (int nf = 0; nf < 4; nf++) {
        int c = wn + nf * 8 + 2 * tig;
        int s0 = wm + g, s1 = s0 + 8;
        Ml[s0][c]     = (c     < s0) ? (accM[nf][0] + accC[nf][0]) * bet[c]     : 0.f;
        Ml[s0][c + 1] = (c + 1 < s0) ? (accM[nf][1] + accC[nf][1]) * bet[c + 1] : 0.f;
        Ml[s1][c]     = (c     < s1) ? (accM[nf][2] + accC[nf][2]) * bet[c]     : 0.f;
        Ml[s1][c + 1] = (c + 1 < s1) ? (accM[nf][3] + accC[nf][3]) * bet[c + 1] : 0.f;
    }
    __syncthreads();
    if (tid < 64) {
        int c = tid;
        X[c][c] = 1.f;
        for (int rr = c + 1; rr < 64; rr++) {
            float s = 0.f;
            for (int m = c; m < rr; m++) s += Ml[rr][m] * X[m][c];
            X[rr][c] = -s;
        }
    }
    __syncthreads();
    float* out = g_Tinv + ((size_t)bh * NBn + i) * 4096;
    for (int e = tid; e < 4096; e += 256) {
        int rr = e >> 6, cc = e & 63;
        out[e] = (rr > cc) ? X[rr][cc] : (rr == cc ? 1.f : 0.f);
    }
}

// ---------------- column-parallel solve (ONE launch, single-sync rounds) ----------------
// Block (j, bh) computes C_ij for i = j..15 sequentially:
//   C_ij = Tinv_i @ ( tril(w_i k_j^T) + sum_{r=j..i-1} (-L_ir) C_rj )
__global__ void solve_kernel() {
    int j = blockIdx.x;
    int bh = blockIdx.y;
    extern __shared__ float smem[];
    float (*stA)[64][68] = (float(*)[64][68])smem;
    float (*stB)[64][68] = (float(*)[64][68])(smem + 2 * STAGE_F);
    EPI_COORDS;
    const float* Lbase = g_L + ((size_t)bh * NBn * NBn) * 4096;
    float* Cbase = g_C + (size_t)bh * Nn * Nn;
    for (int i = j; i < NBn; i++) {
        float accM[4][4] = {}, accC[4][4] = {};
        int R = 1 + (i - j);
        cpa_tile<false>(stA[0], g_w + ((size_t)bh * Nn + i * 64) * HDn, HDn);
        cpa_tile<false>(stB[0], g_k + ((size_t)bh * Nn + j * 64) * HDn, HDn);
        cp_commit();
        for (int r = 0; r < R; r++) {
            cp_wait<0>();
            __syncthreads();
            if (r + 1 < R) {
                int rr = j + r;   // round r+1 consumes block rr
                cpa_tile<false>(stA[(r + 1) & 1], Lbase + ((size_t)(i * NBn + rr)) * 4096, 64);
                cpa_tile<true>(stB[(r + 1) & 1], Cbase + (size_t)(rr * 64) * Nn + j * 64, Nn);
                cp_commit();
            }
            if (r == 0) {
                wtile32<true>(accM, accC, stA[0], stB[0], wm, wn);
                if (i == j) {
#pragma unroll
                    for (int nf = 0; nf < 4; nf++) {
                        int c = wn + nf * 8 + 2 * tig;
                        int r0 = wm + g, r1 = r0 + 8;
                        if (r0 <= c)     { accM[nf][0] = 0.f; accC[nf][0] = 0.f; }
                        if (r0 <= c + 1) { accM[nf][1] = 0.f; accC[nf][1] = 0.f; }
                        if (r1 <= c)     { accM[nf][2] = 0.f; accC[nf][2] = 0.f; }
                        if (r1 <= c + 1) { accM[nf][3] = 0.f; accC[nf][3] = 0.f; }
                    }
                }
            } else {
                wtile32<false>(accM, accC, stA[r & 1], stB[r & 1], wm, wn);
            }
        }
        // finale: C_ij = Tinv_i @ acc
        __syncthreads();   // all warps past last wtile before stB[0]/stA[0] reuse
#pragma unroll
        for (int nf = 0; nf < 4; nf++) {
            int c = wn + nf * 8 + 2 * tig;
            int r0 = wm + g, r1 = r0 + 8;
            stB[0][r0][c]     = accM[nf][0] + accC[nf][0];
            stB[0][r0][c + 1] = accM[nf][1] + accC[nf][1];
            stB[0][r1][c]     = accM[nf][2] + accC[nf][2];
            stB[0][r1][c + 1] = accM[nf][3] + accC[nf][3];
        }
        cpa_tile<false>(stA[0], g_Tinv + ((size_t)bh * NBn + i) * 4096, 64);
        cp_commit(); cp_wait<0>();
        __syncthreads();
        float acc2M[4][4] = {}, acc2C[4][4] = {};
        wtile32<false>(acc2M, acc2C, stA[0], stB[0], wm, wn);
        float* out = Cbase + (size_t)(i * 64) * Nn + j * 64;
#pragma unroll
        for (int nf = 0; nf < 4; nf++) {
            int c = wn + nf * 8 + 2 * tig;
            int r0 = wm + g, r1 = r0 + 8;
            out[r0 * Nn + c]     = acc2M[nf][0] + acc2C[nf][0];
            out[r0 * Nn + c + 1] = acc2M[nf][1] + acc2C[nf][1];
            out[r1 * Nn + c]     = acc2M[nf][2] + acc2C[nf][2];
            out[r1 * Nn + c + 1] = acc2M[nf][3] + acc2C[nf][3];
        }
        __syncthreads();   // C_ij visible + smem free before next i
    }
}

// ---------------- G (NEGATED, dense) ----------------
__global__ void g_kernel() {
    int bx = blockIdx.x;
    int ti = bx >> 4, tj = bx & 15;
    if (tj > ti) return;
    int bh = blockIdx.y;
    extern __shared__ float smem[];
    float (*sA)[68] = (float(*)[68])smem;
    float (*sB)[68] = (float(*)[68])(smem + STAGE_F);
    cpa_tile<false>(sA, g_q + ((size_t)bh * Nn + ti * 64) * HDn, HDn);
    cpa_tile<false>(sB, g_w + ((size_t)bh * Nn + tj * 64) * HDn, HDn);
    cp_commit(); cp_wait<0>();
    __syncthreads();
    EPI_COORDS;
    float accM[4][4] = {}, accC[4][4] = {};
    wtile32<true>(accM, accC, sA, sB, wm, wn);
    float* out = g_G + (size_t)bh * Nn * Nn + (size_t)(ti * 64) * Nn + tj * 64;
    const float* bet = g_beta + bh * Nn + tj * 64;
    bool dg = (ti == tj);
#pragma unroll
    for (int nf = 0; nf < 4; nf++) {
        int c = wn + nf * 8 + 2 * tig;
        int r0 = wm + g, r1 = r0 + 8;
        float v00 = -(accM[nf][0] + accC[nf][0]) * bet[c];
        float v01 = -(accM[nf][1] + accC[nf][1]) * bet[c + 1];
        float v10 = -(accM[nf][2] + accC[nf][2]) * bet[c];
        float v11 = -(accM[nf][3] + accC[nf][3]) * bet[c + 1];
        if (dg) {
            if (c     > r0) v00 = 0.f;
            if (c + 1 > r0) v01 = 0.f;
            if (c     > r1) v10 = 0.f;
            if (c + 1 > r1) v11 = 0.f;
        }
        out[r0 * Nn + c]     = v00;
        out[r0 * Nn + c + 1] = v01;
        out[r1 * Nn + c]     = v10;
        out[r1 * Nn + c + 1] = v11;
    }
}

// ---------------- logits (pipelined, single-sync rounds) ----------------
__global__ void s_kernel() {
    int bx = blockIdx.x;
    int ti = bx >> 4, tj = bx & 15;
    if (tj > ti) return;
    int bh = blockIdx.y;
    extern __shared__ float smem[];
    float (*stA)[64][68] = (float(*)[64][68])smem;
    float (*stB)[64][68] = (float(*)[64][68])(smem + 2 * STAGE_F);
    EPI_COORDS;
    float accM[4][4] = {}, accC[4][4] = {};
    const float* Gp = g_G + (size_t)bh * Nn * Nn + (size_t)(ti * 64) * Nn;
    const float* Cp = g_C + (size_t)bh * Nn * Nn + tj * 64;
    int R = ti - tj + 2;
    cpa_tile<false>(stA[0], g_q + ((size_t)bh * Nn + ti * 64) * HDn, HDn);
    cpa_tile<false>(stB[0], g_k + ((size_t)bh * Nn + tj * 64) * HDn, HDn);
    cp_commit();
    for (int r = 0; r < R; r++) {
        cp_wait<0>();
        __syncthreads();
        if (r + 1 < R) {
            int sb = tj + r;
            cpa_tile<false>(stA[(r + 1) & 1], Gp + sb * 64, Nn);
            cpa_tile<false>(stB[(r + 1) & 1], Cp + (size_t)(sb * 64) * Nn, Nn);
            cp_commit();
        }
        if (r == 0) wtile32<true>(accM, accC, stA[0], stB[0], wm, wn);
        else        wtile32<false>(accM, accC, stA[r & 1], stB[r & 1], wm, wn);
    }
    const float* Fc = g_Fc + bh * Nn;
    float* out = g_S + (size_t)bh * Nn * Nn;
    bool dg = (ti == tj);
#pragma unroll
    for (int nf = 0; nf < 4; nf++) {
        int c = tj * 64 + wn + nf * 8 + 2 * tig;
        int r0 = ti * 64 + wm + g, r1 = r0 + 8;
        float f0 = Fc[r0], f1 = Fc[r1], fc0 = Fc[c], fc1 = Fc[c + 1];
        float v00 = (accM[nf][0] + accC[nf][0]) * 0.125f + f0 - fc0;
        float v01 = (accM[nf][1] + accC[nf][1]) * 0.125f + f0 - fc1;
        float v10 = (accM[nf][2] + accC[nf][2]) * 0.125f + f1 - fc0;
        float v11 = (accM[nf][3] + accC[nf][3]) * 0.125f + f1 - fc1;
        if (dg) {
            if (c     > r0) v00 = -1e30f;
            if (c + 1 > r0) v01 = -1e30f;
            if (c     > r1) v10 = -1e30f;
            if (c + 1 > r1) v11 = -1e30f;
        }
        out[(size_t)r0 * Nn + c]     = v00;
        out[(size_t)r0 * Nn + c + 1] = v01;
        out[(size_t)r1 * Nn + c]     = v10;
        out[(size_t)r1 * Nn + c + 1] = v11;
    }
}

// ---------------- row softmax (in place) ----------------
__global__ void softmax_kernel() {
    int t = blockIdx.x, bh = blockIdx.y, tid = threadIdx.x;
    float* row = g_S + (size_t)bh * Nn * Nn + (size_t)t * Nn;
    int Lr = ((t >> 6) + 1) << 6;
    __shared__ float red[4];
    float m = -3.4e38f;
    for (int idx = tid; idx < Lr; idx += 128) m = fmaxf(m, row[idx]);
#pragma unroll
    for (int o = 16; o; o >>= 1) m = fmaxf(m, __shfl_xor_sync(0xffffffffu, m, o));
    if ((tid & 31) == 0) red[tid >> 5] = m;
    __syncthreads();
    m = fmaxf(fmaxf(red[0], red[1]), fmaxf(red[2], red[3]));
    __syncthreads();
    float s = 0.f;
    for (int idx = tid; idx < Lr; idx += 128) {
        float e = expf(row[idx] - m);
        row[idx] = e;
        s += e;
    }
#pragma unroll
    for (int o = 16; o; o >>= 1) s += __shfl_xor_sync(0xffffffffu, s, o);
    if ((tid & 31) == 0) red[tid >> 5] = s;
    __syncthreads();
    s = red[0] + red[1] + red[2] + red[3];
    float inv = 1.f / s;
    for (int idx = tid; idx < Lr; idx += 128) row[idx] *= inv;
}

// ---------------- o = P @ v (pipelined, single-sync rounds) ----------------
__global__ void pv_kernel() {
    int ti = blockIdx.x, bh = blockIdx.y;
    extern __shared__ float smem[];
    float (*stA)[64][68] = (float(*)[64][68])smem;
    float (*stB)[64][68] = (float(*)[64][68])(smem + 2 * STAGE_F);
    EPI_COORDS;
    float accM[4][4] = {}, accC[4][4] = {};
    const float* Sp = g_S + (size_t)bh * Nn * Nn + (size_t)(ti * 64) * Nn;
    int R = ti + 1;
    cpa_tile<false>(stA[0], Sp, Nn);
    cpa_tile<false>(stB[0], g_v + ((size_t)bh * Nn) * HDn, HDn);
    cp_commit();
    for (int r = 0; r < R; r++) {
        cp_wait<0>();
        __syncthreads();
        if (r + 1 < R) {
            int jb = r + 1;
            cpa_tile<false>(stA[(r + 1) & 1], Sp + jb * 64, Nn);
            cpa_tile<false>(stB[(r + 1) & 1], g_v + ((size_t)bh * Nn + jb * 64) * HDn, HDn);
            cp_commit();
        }
        wtile32<false>(accM, accC, stA[r & 1], stB[r & 1], wm, wn);
    }
    int b = bh >> 4, h = bh & 15;
#pragma unroll
    for (int nf = 0; nf < 4; nf++) {
        int c = h * 64 + wn + nf * 8 + 2 * tig;
        int r0 = b * Nn + ti * 64 + wm + g, r1 = r0 + 8;
        g_o[(size_t)r0 * Dn + c]     = accM[nf][0] + accC[nf][0];
        g_o[(size_t)r0 * Dn + c + 1] = accM[nf][1] + accC[nf][1];
        g_o[(size_t)r1 * Dn + c]     = accM[nf][2] + accC[nf][2];
        g_o[(size_t)r1 * Dn + c + 1] = accM[nf][3] + accC[nf][3];
    }
}

// ---------------- final GEMM: out = o @ Wo (pipelined, single-sync rounds) ----------------
__global__ void out_kernel(const float* __restrict__ Wo, float* __restrict__ C) {
    extern __shared__ float smem[];
    float (*stA)[64][68] = (float(*)[64][68])smem;
    float (*stB)[64][68] = (float(*)[64][68])(smem + 2 * STAGE_F);
    int m0 = blockIdx.y * 64, n0 = blockIdx.x * 64;
    EPI_COORDS;
    float accM[4][4] = {}, accC[4][4] = {};
    cpa_tile<false>(stA[0], g_o + (size_t)m0 * Dn, Dn);
    cpa_tile<false>(stB[0], Wo + n0, Dn);
    cp_commit();
    for (int r = 0; r < 16; r++) {
        cp_wait<0>();
        __syncthreads();
        if (r + 1 < 16) {
            cpa_tile<false>(stA[(r + 1) & 1], g_o + (size_t)m0 * Dn + (r + 1) * 64, Dn);
            cpa_tile<false>(stB[(r + 1) & 1], Wo + (size_t)((r + 1) * 64) * Dn + n0, Dn);
            cp_commit();
        }
        wtile32<false>(accM, accC, stA[r & 1], stB[r & 1], wm, wn);
    }
#pragma unroll
    for (int nf = 0; nf < 4; nf++) {
        int col = n0 + wn + nf * 8 + 2 * tig;
        int r0 = m0 + wm + g, r1 = r0 + 8;
        C[(size_t)r0 * Dn + col]     = accM[nf][0] + accC[nf][0];
        C[(size_t)r0 * Dn + col + 1] = accM[nf][1] + accC[nf][1];
        C[(size_t)r1 * Dn + col]     = accM[nf][2] + accC[nf][2];
        C[(size_t)r1 * Dn + col + 1] = accM[nf][3] + accC[nf][3];
    }
}

// ---------------- launch ----------------
extern "C" void kernel_launch(void* const* d_in, const int* in_sizes, int n_in,
                              void* d_out, int out_size) {
    const float* x   = (const float*)d_in[0];
    const float* Wq  = (const float*)d_in[1];
    const float* Wk  = (const float*)d_in[2];
    const float* Wv  = (const float*)d_in[3];
    const float* Wo  = (const float*)d_in[4];
    const float* Ww1 = (const float*)d_in[5];
    const float* Ww2 = (const float*)d_in[6];
    const float* Wb  = (const float*)d_in[7];
    const float* Wf  = (const float*)d_in[8];
    const float* dl  = (const float*)d_in[9];
    float* out = (float*)d_out;

    const int SM_BF = (64 * 128 + 128 * 32) * (int)sizeof(float);

    static float *Ww;
    static bool init = false;
    if (!init) {
        void* p;
        cudaGetSymbolAddress(&p, g_Ww); Ww = (float*)p;
        cudaFuncSetAttribute(proj_kernel,  cudaFuncAttributeMaxDynamicSharedMemorySize, SM_PIPE);
        cudaFuncSetAttribute(solve_kernel, cudaFuncAttributeMaxDynamicSharedMemorySize, SM_PIPE);
        cudaFuncSetAttribute(s_kernel,     cudaFuncAttributeMaxDynamicSharedMemorySize, SM_PIPE);
        cudaFuncSetAttribute(pv_kernel,    cudaFuncAttributeMaxDynamicSharedMemorySize, SM_PIPE);
        cudaFuncSetAttribute(out_kernel,   cudaFuncAttributeMaxDynamicSharedMemorySize, SM_PIPE);
        cudaFuncSetAttribute(tinv_kernel,  cudaFuncAttributeMaxDynamicSharedMemorySize, SM_TINV);
        cudaFuncSetAttribute(l_kernel,     cudaFuncAttributeMaxDynamicSharedMemorySize, SM_ONE);
        cudaFuncSetAttribute(g_kernel,     cudaFuncAttributeMaxDynamicSharedMemorySize, SM_ONE);
        cudaFuncSetAttribute(bf_kernel,    cudaFuncAttributeMaxDynamicSharedMemorySize, SM_BF);
        init = true;
    }

    dim3 thr(256);

    gemm_kernel<<<dim3(16, 16), thr>>>(Ww1, Ww2, Ww, Dn, Dn, HDn);
    bf_kernel<<<dim3(32, 8), thr, SM_BF>>>(x, Wb, Wf);
    gate_kernel<<<32, thr>>>(dl);

    proj_kernel<<<dim3(16, 32, 4), thr, SM_PIPE>>>(x, Wq, Wk, Wv);

    l_kernel<<<dim3(256, 32), thr, SM_ONE>>>();
    tinv_kernel<<<dim3(16, 32), thr, SM_TINV>>>();

    solve_kernel<<<dim3(NBn, BHn), thr, SM_PIPE>>>();   // single launch, column-parallel

    g_kernel<<<dim3(256, 32), thr, SM_ONE>>>();
    s_kernel<<<dim3(256, 32), thr, SM_PIPE>>>();
    softmax_kernel<<<dim3(1024, 32), dim3(128)>>>();
    pv_kernel<<<dim3(16, 32), thr, SM_PIPE>>>();

    out_kernel<<<dim3(16, 32), thr, SM_PIPE>>>(Wo, out);
}

// round 15
// speedup vs baseline: 1.0233x; 1.0233x over previous
#include <cuda_runtime.h>
#include <math.h>

// Problem constants
#define Bn 2
#define Nn 1024
#define Dn 1024
#define Hn 16
#define HDn 64
#define BHn 32
#define NBn 16

typedef float2 f2;

// ---------------- device scratch (all fp32) ----------------
__device__ float g_Ww[Dn*Dn];                   // Ww1@Ww2
__device__ float g_bf[8*2048*32];               // K-split partials of x@[Wb|Wf]
__device__ float g_beta[BHn*Nn];
__device__ float g_Fc[BHn*Nn];
__device__ float g_q[BHn*Nn*HDn];               // head-major [bh][n][hd]
__device__ float g_v[BHn*Nn*HDn];
__device__ float g_w[BHn*Nn*HDn];               // l2-normalized [bh][n][hd]
__device__ float g_kT[(size_t)BHn*HDn*Nn];      // k TRANSPOSED [bh][hd][n]
__device__ float g_wT[(size_t)BHn*HDn*Nn];      // w TRANSPOSED [bh][hd][n]
__device__ float g_Tinv[BHn*NBn*4096];
__device__ float g_L[(size_t)BHn*NBn*NBn*4096]; // NEGATED L, blocked 64x64
__device__ float g_C[(size_t)BHn*Nn*Nn];
__device__ float g_G[(size_t)BHn*Nn*Nn];        // NEGATED G, dense
__device__ float g_S[(size_t)BHn*Nn*Nn];        // logits -> P in place
__device__ float g_o[Bn*Nn*Dn];

// ---------------- tf32 split + mma ----------------
// 2-instruction split (R12-verified): hi = rna(x), lo = x - hi passed raw.
__device__ __forceinline__ f2 splt(float x) {
    unsigned h;
    asm("cvt.rna.tf32.f32 %0, %1;" : "=r"(h) : "f"(x));
    float hf = __uint_as_float(h);
    return make_float2(hf, x - hf);
}

__device__ __forceinline__ void mma_raw(float c[4], float a0, float a1, float a2, float a3,
                                        float b0, float b1) {
    unsigned A0 = __float_as_uint(a0), A1 = __float_as_uint(a1);
    unsigned A2 = __float_as_uint(a2), A3 = __float_as_uint(a3);
    unsigned B0 = __float_as_uint(b0), B1 = __float_as_uint(b1);
    asm volatile(
        "mma.sync.aligned.m16n8k8.row.col.f32.tf32.tf32.f32 "
        "{%0,%1,%2,%3}, {%4,%5,%6,%7}, {%8,%9}, {%0,%1,%2,%3};"
        : "+f"(c[0]), "+f"(c[1]), "+f"(c[2]), "+f"(c[3])
        : "r"(A0), "r"(A1), "r"(A2), "r"(A3), "r"(B0), "r"(B1));
}

// NN-only warp tile: 16x32 region of 64x64x64 product. A[m][k], B[k][n], stride 72.
// Stride 72 == 8 mod 32 banks -> A reads bank 8g+tig, B reads bank 8tig+g:
// both bijective over the warp -> conflict-free.
__device__ __forceinline__ void wtile32(float acc[4][4], const float (*A)[72], const float (*B)[72],
                                        int m0, int n0) {
    int lane = threadIdx.x & 31;
    int g = lane >> 2, tig = lane & 3;
#pragma unroll
    for (int k0 = 0; k0 < 64; k0 += 8) {
        f2 A0 = splt(A[m0 + g][k0 + tig]);
        f2 A1 = splt(A[m0 + g + 8][k0 + tig]);
        f2 A2 = splt(A[m0 + g][k0 + tig + 4]);
        f2 A3 = splt(A[m0 + g + 8][k0 + tig + 4]);
#pragma unroll
        for (int nf = 0; nf < 4; nf++) {
            int nn = n0 + nf * 8 + g;
            f2 B0 = splt(B[k0 + tig][nn]);
            f2 B1 = splt(B[k0 + tig + 4][nn]);
            mma_raw(acc[nf], A0.x, A1.x, A2.x, A3.x, B0.x, B1.x);
            mma_raw(acc[nf], A0.x, A1.x, A2.x, A3.x, B0.y, B1.y);
            mma_raw(acc[nf], A0.y, A1.y, A2.y, A3.y, B0.x, B1.x);
        }
    }
}

// ---------------- cp.async helpers ----------------
__device__ __forceinline__ void cp16(void* sdst, const void* gsrc) {
    unsigned s = (unsigned)__cvta_generic_to_shared(sdst);
    asm volatile("cp.async.ca.shared.global [%0], [%1], 16;" :: "r"(s), "l"(gsrc));
}
__device__ __forceinline__ void cp16cg(void* sdst, const void* gsrc) {
    unsigned s = (unsigned)__cvta_generic_to_shared(sdst);
    asm volatile("cp.async.cg.shared.global [%0], [%1], 16;" :: "r"(s), "l"(gsrc));
}
__device__ __forceinline__ void cp_commit() { asm volatile("cp.async.commit_group;"); }
template<int N> __device__ __forceinline__ void cp_wait() {
    asm volatile("cp.async.wait_group %0;" :: "n"(N));
}

// Async-copy a 64x64 fp32 tile (row stride in floats, multiple of 4) into stride-72 smem.
template<bool CG>
__device__ __forceinline__ void cpa_tile(float (*sm)[72], const float* __restrict__ g, int stride) {
    int t = threadIdx.x;
    int r = t >> 2;
    int c4 = (t & 3) << 4;
    const float* gp = g + (size_t)r * stride + c4;
#pragma unroll
    for (int q = 0; q < 4; q++) {
        if (CG) cp16cg(&sm[r][c4 + 4*q], gp + 4*q);
        else    cp16  (&sm[r][c4 + 4*q], gp + 4*q);
    }
}

#define EPI_COORDS \
    int lane = threadIdx.x & 31, wrp = threadIdx.x >> 5; \
    int g = lane >> 2, tig = lane & 3; \
    int wm = (wrp & 3) * 16, wn = (wrp >> 2) * 32; \
    (void)g; (void)tig; (void)wm; (void)wn;

#define STAGE_F (64 * 72)                            // 4608 floats
#define SM_PIPE (4 * STAGE_F * (int)sizeof(float))   // 73728 B
#define SM_ONE  (2 * STAGE_F * (int)sizeof(float))   // 36864 B
#define SM_TINV ((2 * STAGE_F + 2 * 64 * 65) * (int)sizeof(float))  // 70144 B

// ---------------- scalar GEMM (Ww only) ----------------
__global__ void gemm_kernel(const float* __restrict__ A, const float* __restrict__ Bm,
                            float* __restrict__ C, int M, int Ncols, int K) {
    __shared__ float As[16][65];
    __shared__ float Bs[16][65];
    int m0 = blockIdx.y * 64, n0 = blockIdx.x * 64;
    int tid = threadIdx.x;
    int ty = (tid >> 4) << 2, tx = (tid & 15) << 2;
    int lrA = tid >> 2, lcA = (tid & 3) << 2;
    int krB = tid >> 4, ncB = (tid & 15) << 2;
    float acc[4][4] = {};
    for (int k0 = 0; k0 < K; k0 += 16) {
        float4 va = *(const float4*)(A + (size_t)(m0 + lrA) * K + k0 + lcA);
        As[lcA + 0][lrA] = va.x;
        As[lcA + 1][lrA] = va.y;
        As[lcA + 2][lrA] = va.z;
        As[lcA + 3][lrA] = va.w;
#pragma unroll
        for (int q = 0; q < 4; q++)
            Bs[krB][ncB + q] = Bm[(size_t)(k0 + krB) * Ncols + n0 + ncB + q];
        __syncthreads();
#pragma unroll
        for (int kk = 0; kk < 16; kk++) {
            float a[4], b[4];
#pragma unroll
            for (int i = 0; i < 4; i++) a[i] = As[kk][ty + i];
#pragma unroll
            for (int j = 0; j < 4; j++) b[j] = Bs[kk][tx + j];
#pragma unroll
            for (int i = 0; i < 4; i++)
#pragma unroll
                for (int j = 0; j < 4; j++)
                    acc[i][j] += a[i] * b[j];
        }
        __syncthreads();
    }
#pragma unroll
    for (int i = 0; i < 4; i++)
#pragma unroll
        for (int j = 0; j < 4; j++)
            C[(size_t)(m0 + ty + i) * Ncols + n0 + tx + j] = acc[i][j];
}

// ---------------- K-split partials of x @ [Wb|Wf] ----------------
__global__ void bf_kernel(const float* __restrict__ x, const float* __restrict__ Wb,
                          const float* __restrict__ Wf) {
    extern __shared__ float dsm[];
    float* xs = dsm;              // [64][128]
    float* Bs = dsm + 64 * 128;   // [128][32]
    int m0 = blockIdx.x * 64;
    int kz = blockIdx.y;
    int tid = threadIdx.x;
    for (int idx = tid; idx < 128 * 32; idx += 256) {
        int k = idx >> 5, c = idx & 31;
        int kg = kz * 128 + k;
        Bs[idx] = (c < 16) ? Wb[kg * 16 + c] : Wf[kg * 16 + (c - 16)];
    }
    for (int idx = tid * 4; idx < 64 * 128; idx += 1024) {
        int r = idx >> 7, k = idx & 127;
        *(float4*)&xs[idx] = *(const float4*)(x + (size_t)(m0 + r) * Dn + kz * 128 + k);
    }
    __syncthreads();
    int tx = tid & 31, ry = tid >> 5;
    float acc[8] = {};
    for (int k = 0; k < 128; k++) {
        float bv = Bs[k * 32 + tx];
#pragma unroll
        for (int s = 0; s < 8; s++)
            acc[s] += xs[(ry + 8 * s) * 128 + k] * bv;
    }
#pragma unroll
    for (int s = 0; s < 8; s++)
        g_bf[((size_t)kz * 2048 + m0 + ry + 8 * s) * 32 + tx] = acc[s];
}

// ---------------- gates ----------------
__global__ void gate_kernel(const float* __restrict__ delta) {
    int bh = blockIdx.x, tid = threadIdx.x;
    int b = bh >> 4, h = bh & 15;
    __shared__ float part[256];
    float v[4];
#pragma unroll
    for (int u = 0; u < 4; u++) {
        int n = tid * 4 + u;
        int row = (b << 10) + n;
        float bbv = 0.f, ffv = 0.f;
#pragma unroll
        for (int z = 0; z < 8; z++) {
            bbv += g_bf[((size_t)z * 2048 + row) * 32 + h];
            ffv += g_bf[((size_t)z * 2048 + row) * 32 + 16 + h];
        }
        g_beta[bh * Nn + n] = 2.f / (1.f + expf(-bbv));
        float z2 = ffv + delta[h];
        v[u] = fminf(z2, 0.f) - log1pf(expf(-fabsf(z2)));
    }
    v[1] += v[0]; v[2] += v[1]; v[3] += v[2];
    part[tid] = v[3];
    __syncthreads();
    if (tid == 0) {
        float run = 0.f;
        for (int t = 0; t < 256; t++) { float tmp = part[t]; part[t] = run; run += tmp; }
    }
    __syncthreads();
    float off = part[tid];
#pragma unroll
    for (int u = 0; u < 4; u++)
        g_Fc[bh * Nn + tid * 4 + u] = off + v[u];
}

// ---------------- fused projections q/k/v/w (pipelined) ----------------
// z==0 -> q (row-major), z==1 -> kT (transposed), z==2 -> v (row-major),
// z==3 -> w (row-major, normalized) + wT (transposed).
__global__ void proj_kernel(const float* __restrict__ x, const float* __restrict__ Wq,
                            const float* __restrict__ Wk, const float* __restrict__ Wv) {
    int h = blockIdx.x, mt = blockIdx.y, z = blockIdx.z;
    const float* W = (z == 0) ? Wq : (z == 1) ? Wk : (z == 2) ? Wv : g_Ww;
    extern __shared__ float smem[];
    float (*stA)[64][72] = (float(*)[64][72])smem;
    float (*stB)[64][72] = (float(*)[64][72])(smem + 2 * STAGE_F);
    int m0 = mt * 64, n0 = h * 64;
    EPI_COORDS;
    float acc[4][4] = {};
    cpa_tile<false>(stA[0], x + (size_t)m0 * Dn, Dn);
    cpa_tile<false>(stB[0], W + n0, Dn);
    cp_commit();
    for (int r = 0; r < 16; r++) {
        if (r + 1 < 16) {
            cpa_tile<false>(stA[(r + 1) & 1], x + (size_t)m0 * Dn + (r + 1) * 64, Dn);
            cpa_tile<false>(stB[(r + 1) & 1], W + (size_t)((r + 1) * 64) * Dn + n0, Dn);
            cp_commit();
            cp_wait<1>();
        } else cp_wait<0>();
        __syncthreads();
        wtile32(acc, stA[r & 1], stB[r & 1], wm, wn);
        __syncthreads();
    }
    int b = m0 >> 10;
    int nbase = m0 & 1023;
    if (z == 0 || z == 2) {
        float* dst = ((z == 0) ? g_q : g_v) + ((size_t)(b * Hn + h) * Nn) * HDn;
#pragma unroll
        for (int nf = 0; nf < 4; nf++) {
            int c = wn + nf * 8 + 2 * tig;
            int r0 = wm + g, r1 = r0 + 8;
            dst[(size_t)(nbase + r0) * HDn + c]     = acc[nf][0];
            dst[(size_t)(nbase + r0) * HDn + c + 1] = acc[nf][1];
            dst[(size_t)(nbase + r1) * HDn + c]     = acc[nf][2];
            dst[(size_t)(nbase + r1) * HDn + c + 1] = acc[nf][3];
        }
    } else if (z == 1) {
        // k: transposed only
        float* dstT = g_kT + (size_t)(b * Hn + h) * HDn * Nn;
#pragma unroll
        for (int nf = 0; nf < 4; nf++) {
            int c = wn + nf * 8 + 2 * tig;
            int r0 = wm + g, r1 = r0 + 8;
            dstT[(size_t)c * Nn + nbase + r0]       = acc[nf][0];
            dstT[(size_t)(c + 1) * Nn + nbase + r0] = acc[nf][1];
            dstT[(size_t)c * Nn + nbase + r1]       = acc[nf][2];
            dstT[(size_t)(c + 1) * Nn + nbase + r1] = acc[nf][3];
        }
    } else {
        // w: stage fp32, l2-normalize rows, write row-major AND transposed
        float (*sT)[72] = stA[0];
        __shared__ float rnorm[64];
#pragma unroll
        for (int nf = 0; nf < 4; nf++) {
            int c = wn + nf * 8 + 2 * tig;
            int r0 = wm + g, r1 = r0 + 8;
            sT[r0][c]     = acc[nf][0];
            sT[r0][c + 1] = acc[nf][1];
            sT[r1][c]     = acc[nf][2];
            sT[r1][c + 1] = acc[nf][3];
        }
        __syncthreads();
        if (threadIdx.x < 64) {
            float s = 1e-6f;
            for (int c = 0; c < 64; c++) { float w = sT[threadIdx.x][c]; s += w * w; }
            rnorm[threadIdx.x] = rsqrtf(s);
        }
        __syncthreads();
        float* dst  = g_w  + ((size_t)(b * Hn + h) * Nn) * HDn;
        float* dstT = g_wT + (size_t)(b * Hn + h) * HDn * Nn;
#pragma unroll
        for (int nf = 0; nf < 4; nf++) {
            int c = wn + nf * 8 + 2 * tig;
            int r0 = wm + g, r1 = r0 + 8;
            float v00 = sT[r0][c]     * rnorm[r0];
            float v01 = sT[r0][c + 1] * rnorm[r0];
            float v10 = sT[r1][c]     * rnorm[r1];
            float v11 = sT[r1][c + 1] * rnorm[r1];
            dst[(size_t)(nbase + r0) * HDn + c]     = v00;
            dst[(size_t)(nbase + r0) * HDn + c + 1] = v01;
            dst[(size_t)(nbase + r1) * HDn + c]     = v10;
            dst[(size_t)(nbase + r1) * HDn + c + 1] = v11;
            dstT[(size_t)c * Nn + nbase + r0]       = v00;
            dstT[(size_t)(c + 1) * Nn + nbase + r0] = v01;
            dstT[(size_t)c * Nn + nbase + r1]       = v10;
            dstT[(size_t)(c + 1) * Nn + nbase + r1] = v11;
        }
    }
}

// ---------------- L blocks (NEGATED): A=w_i, B=wT col r -> NN ----------------
__global__ void l_kernel() {
    int bx = blockIdx.x;
    int i = bx >> 4, r = bx & 15;
    if (r >= i) return;
    int bh = blockIdx.y;
    extern __shared__ float smem[];
    float (*sA)[72] = (float(*)[72])smem;
    float (*sB)[72] = (float(*)[72])(smem + STAGE_F);
    cpa_tile<false>(sA, g_w + ((size_t)bh * Nn + i * 64) * HDn, HDn);
    cpa_tile<false>(sB, g_wT + (size_t)bh * HDn * Nn + r * 64, Nn);
    cp_commit(); cp_wait<0>();
    __syncthreads();
    EPI_COORDS;
    float acc[4][4] = {};
    wtile32(acc, sA, sB, wm, wn);
    float* out = g_L + (((size_t)bh * NBn + i) * NBn + r) * 4096;
    const float* bet = g_beta + bh * Nn + r * 64;
#pragma unroll
    for (int nf = 0; nf < 4; nf++) {
        int c = wn + nf * 8 + 2 * tig;
        int r0 = wm + g, r1 = r0 + 8;
        out[r0 * 64 + c]     = -acc[nf][0] * bet[c];
        out[r0 * 64 + c + 1] = -acc[nf][1] * bet[c + 1];
        out[r1 * 64 + c]     = -acc[nf][2] * bet[c];
        out[r1 * 64 + c + 1] = -acc[nf][3] * bet[c + 1];
    }
}

// ---------------- Tinv = (I + L_ii)^-1: A=w_i, B=wT col i -> NN ----------------
__global__ void tinv_kernel() {
    int i = blockIdx.x, bh = blockIdx.y, tid = threadIdx.x;
    extern __shared__ float smem[];
    float (*sA)[72] = (float(*)[72])smem;
    float (*sB)[72] = (float(*)[72])(smem + STAGE_F);
    float (*Ml)[65] = (float(*)[65])(smem + 2 * STAGE_F);
    float (*X)[65]  = (float(*)[65])(smem + 2 * STAGE_F + 64 * 65);
    cpa_tile<false>(sA, g_w + ((size_t)bh * Nn + i * 64) * HDn, HDn);
    cpa_tile<false>(sB, g_wT + (size_t)bh * HDn * Nn + i * 64, Nn);
    cp_commit(); cp_wait<0>();
    __syncthreads();
    EPI_COORDS;
    float acc[4][4] = {};
    wtile32(acc, sA, sB, wm, wn);
    const float* bet = g_beta + bh * Nn + i * 64;
#pragma unroll
    for (int nf = 0; nf < 4; nf++) {
        int c = wn + nf * 8 + 2 * tig;
        int s0 = wm + g, s1 = s0 + 8;
        Ml[s0][c]     = (c     < s0) ? acc[nf][0] * bet[c]     : 0.f;
        Ml[s0][c + 1] = (c + 1 < s0) ? acc[nf][1] * bet[c + 1] : 0.f;
        Ml[s1][c]     = (c     < s1) ? acc[nf][2] * bet[c]     : 0.f;
        Ml[s1][c + 1] = (c + 1 < s1) ? acc[nf][3] * bet[c + 1] : 0.f;
    }
    __syncthreads();
    if (tid < 64) {
        int c = tid;
        X[c][c] = 1.f;
        for (int rr = c + 1; rr < 64; rr++) {
            float s = 0.f;
            for (int m = c; m < rr; m++) s += Ml[rr][m] * X[m][c];
            X[rr][c] = -s;
        }
    }
    __syncthreads();
    float* out = g_Tinv + ((size_t)bh * NBn + i) * 4096;
    for (int e = tid; e < 4096; e += 256) {
        int rr = e >> 6, cc = e & 63;
        out[e] = (rr > cc) ? X[rr][cc] : (rr == cc ? 1.f : 0.f);
    }
}

// ---------------- column-parallel solve (ONE launch, all-NN rounds) ----------------
// Block (j, bh) computes C_ij for i = j..15 sequentially:
//   C_ij = Tinv_i @ ( tril(w_i kT_j) + sum_{r=j..i-1} (-L_ir) C_rj )
__global__ void solve_kernel() {
    int j = blockIdx.x;
    int bh = blockIdx.y;
    extern __shared__ float smem[];
    float (*stA)[64][72] = (float(*)[64][72])smem;
    float (*stB)[64][72] = (float(*)[64][72])(smem + 2 * STAGE_F);
    EPI_COORDS;
    const float* Lbase = g_L + ((size_t)bh * NBn * NBn) * 4096;
    float* Cbase = g_C + (size_t)bh * Nn * Nn;
    for (int i = j; i < NBn; i++) {
        float acc[4][4] = {};
        int R = 1 + (i - j);
        cpa_tile<false>(stA[0], g_w + ((size_t)bh * Nn + i * 64) * HDn, HDn);
        cpa_tile<false>(stB[0], g_kT + (size_t)bh * HDn * Nn + j * 64, Nn);
        cp_commit();
        for (int r = 0; r < R; r++) {
            if (r + 1 < R) {
                int rr = j + r;   // round r+1 consumes block rr
                cpa_tile<false>(stA[(r + 1) & 1], Lbase + ((size_t)(i * NBn + rr)) * 4096, 64);
                cpa_tile<true>(stB[(r + 1) & 1], Cbase + (size_t)(rr * 64) * Nn + j * 64, Nn);
                cp_commit();
                cp_wait<1>();
            } else cp_wait<0>();
            __syncthreads();
            wtile32(acc, stA[r & 1], stB[r & 1], wm, wn);
            if (r == 0 && i == j) {
#pragma unroll
                for (int nf = 0; nf < 4; nf++) {
                    int c = wn + nf * 8 + 2 * tig;
                    int r0 = wm + g, r1 = r0 + 8;
                    if (r0 <= c)     acc[nf][0] = 0.f;
                    if (r0 <= c + 1) acc[nf][1] = 0.f;
                    if (r1 <= c)     acc[nf][2] = 0.f;
                    if (r1 <= c + 1) acc[nf][3] = 0.f;
                }
            }
            __syncthreads();
        }
        // finale: C_ij = Tinv_i @ acc
#pragma unroll
        for (int nf = 0; nf < 4; nf++) {
            int c = wn + nf * 8 + 2 * tig;
            int r0 = wm + g, r1 = r0 + 8;
            stB[0][r0][c]     = acc[nf][0];
            stB[0][r0][c + 1] = acc[nf][1];
            stB[0][r1][c]     = acc[nf][2];
            stB[0][r1][c + 1] = acc[nf][3];
        }
        cpa_tile<false>(stA[0], g_Tinv + ((size_t)bh * NBn + i) * 4096, 64);
        cp_commit(); cp_wait<0>();
        __syncthreads();
        float acc2[4][4] = {};
        wtile32(acc2, stA[0], stB[0], wm, wn);
        float* out = Cbase + (size_t)(i * 64) * Nn + j * 64;
#pragma unroll
        for (int nf = 0; nf < 4; nf++) {
            int c = wn + nf * 8 + 2 * tig;
            int r0 = wm + g, r1 = r0 + 8;
            out[r0 * Nn + c]     = acc2[nf][0];
            out[r0 * Nn + c + 1] = acc2[nf][1];
            out[r1 * Nn + c]     = acc2[nf][2];
            out[r1 * Nn + c + 1] = acc2[nf][3];
        }
        __syncthreads();   // C_ij visible to the block before next i reads it
    }
}

// ---------------- G (NEGATED, dense): A=q, B=wT col tj -> NN ----------------
__global__ void g_kernel() {
    int bx = blockIdx.x;
    int ti = bx >> 4, tj = bx & 15;
    if (tj > ti) return;
    int bh = blockIdx.y;
    extern __shared__ float smem[];
    float (*sA)[72] = (float(*)[72])smem;
    float (*sB)[72] = (float(*)[72])(smem + STAGE_F);
    cpa_tile<false>(sA, g_q + ((size_t)bh * Nn + ti * 64) * HDn, HDn);
    cpa_tile<false>(sB, g_wT + (size_t)bh * HDn * Nn + tj * 64, Nn);
    cp_commit(); cp_wait<0>();
    __syncthreads();
    EPI_COORDS;
    float acc[4][4] = {};
    wtile32(acc, sA, sB, wm, wn);
    float* out = g_G + (size_t)bh * Nn * Nn + (size_t)(ti * 64) * Nn + tj * 64;
    const float* bet = g_beta + bh * Nn + tj * 64;
    bool dg = (ti == tj);
#pragma unroll
    for (int nf = 0; nf < 4; nf++) {
        int c = wn + nf * 8 + 2 * tig;
        int r0 = wm + g, r1 = r0 + 8;
        float v00 = -acc[nf][0] * bet[c];
        float v01 = -acc[nf][1] * bet[c + 1];
        float v10 = -acc[nf][2] * bet[c];
        float v11 = -acc[nf][3] * bet[c + 1];
        if (dg) {
            if (c     > r0) v00 = 0.f;
            if (c + 1 > r0) v01 = 0.f;
            if (c     > r1) v10 = 0.f;
            if (c + 1 > r1) v11 = 0.f;
        }
        out[r0 * Nn + c]     = v00;
        out[r0 * Nn + c + 1] = v01;
        out[r1 * Nn + c]     = v10;
        out[r1 * Nn + c + 1] = v11;
    }
}

// ---------------- logits (pipelined, all-NN rounds) ----------------
__global__ void s_kernel() {
    int bx = blockIdx.x;
    int ti = bx >> 4, tj = bx & 15;
    if (tj > ti) return;
    int bh = blockIdx.y;
    extern __shared__ float smem[];
    float (*stA)[64][72] = (float(*)[64][72])smem;
    float (*stB)[64][72] = (float(*)[64][72])(smem + 2 * STAGE_F);
    EPI_COORDS;
    float acc[4][4] = {};
    const float* Gp = g_G + (size_t)bh * Nn * Nn + (size_t)(ti * 64) * Nn;
    const float* Cp = g_C + (size_t)bh * Nn * Nn + tj * 64;
    int R = ti - tj + 2;
    cpa_tile<false>(stA[0], g_q + ((size_t)bh * Nn + ti * 64) * HDn, HDn);
    cpa_tile<false>(stB[0], g_kT + (size_t)bh * HDn * Nn + tj * 64, Nn);
    cp_commit();
    for (int r = 0; r < R; r++) {
        if (r + 1 < R) {
            int sb = tj + r;
            cpa_tile<false>(stA[(r + 1) & 1], Gp + sb * 64, Nn);
            cpa_tile<false>(stB[(r + 1) & 1], Cp + (size_t)(sb * 64) * Nn, Nn);
            cp_commit();
            cp_wait<1>();
        } else cp_wait<0>();
        __syncthreads();
        wtile32(acc, stA[r & 1], stB[r & 1], wm, wn);
        __syncthreads();
    }
    const float* Fc = g_Fc + bh * Nn;
    float* out = g_S + (size_t)bh * Nn * Nn;
    bool dg = (ti == tj);
#pragma unroll
    for (int nf = 0; nf < 4; nf++) {
        int c = tj * 64 + wn + nf * 8 + 2 * tig;
        int r0 = ti * 64 + wm + g, r1 = r0 + 8;
        float f0 = Fc[r0], f1 = Fc[r1], fc0 = Fc[c], fc1 = Fc[c + 1];
        float v00 = acc[nf][0] * 0.125f + f0 - fc0;
        float v01 = acc[nf][1] * 0.125f + f0 - fc1;
        float v10 = acc[nf][2] * 0.125f + f1 - fc0;
        float v11 = acc[nf][3] * 0.125f + f1 - fc1;
        if (dg) {
            if (c     > r0) v00 = -1e30f;
            if (c + 1 > r0) v01 = -1e30f;
            if (c     > r1) v10 = -1e30f;
            if (c + 1 > r1) v11 = -1e30f;
        }
        out[(size_t)r0 * Nn + c]     = v00;
        out[(size_t)r0 * Nn + c + 1] = v01;
        out[(size_t)r1 * Nn + c]     = v10;
        out[(size_t)r1 * Nn + c + 1] = v11;
    }
}

// ---------------- row softmax (in place) ----------------
__global__ void softmax_kernel() {
    int t = blockIdx.x, bh = blockIdx.y, tid = threadIdx.x;
    float* row = g_S + (size_t)bh * Nn * Nn + (size_t)t * Nn;
    int Lr = ((t >> 6) + 1) << 6;
    __shared__ float red[4];
    float m = -3.4e38f;
    for (int idx = tid; idx < Lr; idx += 128) m = fmaxf(m, row[idx]);
#pragma unroll
    for (int o = 16; o; o >>= 1) m = fmaxf(m, __shfl_xor_sync(0xffffffffu, m, o));
    if ((tid & 31) == 0) red[tid >> 5] = m;
    __syncthreads();
    m = fmaxf(fmaxf(red[0], red[1]), fmaxf(red[2], red[3]));
    __syncthreads();
    float s = 0.f;
    for (int idx = tid; idx < Lr; idx += 128) {
        float e = expf(row[idx] - m);
        row[idx] = e;
        s += e;
    }
#pragma unroll
    for (int o = 16; o; o >>= 1) s += __shfl_xor_sync(0xffffffffu, s, o);
    if ((tid & 31) == 0) red[tid >> 5] = s;
    __syncthreads();
    s = red[0] + red[1] + red[2] + red[3];
    float inv = 1.f / s;
    for (int idx = tid; idx < Lr; idx += 128) row[idx] *= inv;
}

// ---------------- o = P @ v (pipelined) ----------------
__global__ void pv_kernel() {
    int ti = blockIdx.x, bh = blockIdx.y;
    extern __shared__ float smem[];
    float (*stA)[64][72] = (float(*)[64][72])smem;
    float (*stB)[64][72] = (float(*)[64][72])(smem + 2 * STAGE_F);
    EPI_COORDS;
    float acc[4][4] = {};
    const float* Sp = g_S + (size_t)bh * Nn * Nn + (size_t)(ti * 64) * Nn;
    int R = ti + 1;
    cpa_tile<false>(stA[0], Sp, Nn);
    cpa_tile<false>(stB[0], g_v + ((size_t)bh * Nn) * HDn, HDn);
    cp_commit();
    for (int r = 0; r < R; r++) {
        if (r + 1 < R) {
            int jb = r + 1;
            cpa_tile<false>(stA[(r + 1) & 1], Sp + jb * 64, Nn);
            cpa_tile<false>(stB[(r + 1) & 1], g_v + ((size_t)bh * Nn + jb * 64) * HDn, HDn);
            cp_commit();
            cp_wait<1>();
        } else cp_wait<0>();
        __syncthreads();
        wtile32(acc, stA[r & 1], stB[r & 1], wm, wn);
        __syncthreads();
    }
    int b = bh >> 4, h = bh & 15;
#pragma unroll
    for (int nf = 0; nf < 4; nf++) {
        int c = h * 64 + wn + nf * 8 + 2 * tig;
        int r0 = b * Nn + ti * 64 + wm + g, r1 = r0 + 8;
        g_o[(size_t)r0 * Dn + c]     = acc[nf][0];
        g_o[(size_t)r0 * Dn + c + 1] = acc[nf][1];
        g_o[(size_t)r1 * Dn + c]     = acc[nf][2];
        g_o[(size_t)r1 * Dn + c + 1] = acc[nf][3];
    }
}

// ---------------- final GEMM: out = o @ Wo (pipelined) ----------------
__global__ void out_kernel(const float* __restrict__ Wo, float* __restrict__ C) {
    extern __shared__ float smem[];
    float (*stA)[64][72] = (float(*)[64][72])smem;
    float (*stB)[64][72] = (float(*)[64][72])(smem + 2 * STAGE_F);
    int m0 = blockIdx.y * 64, n0 = blockIdx.x * 64;
    EPI_COORDS;
    float acc[4][4] = {};
    cpa_tile<false>(stA[0], g_o + (size_t)m0 * Dn, Dn);
    cpa_tile<false>(stB[0], Wo + n0, Dn);
    cp_commit();
    for (int r = 0; r < 16; r++) {
        if (r + 1 < 16) {
            cpa_tile<false>(stA[(r + 1) & 1], g_o + (size_t)m0 * Dn + (r + 1) * 64, Dn);
            cpa_tile<false>(stB[(r + 1) & 1], Wo + (size_t)((r + 1) * 64) * Dn + n0, Dn);
            cp_commit();
            cp_wait<1>();
        } else cp_wait<0>();
        __syncthreads();
        wtile32(acc, stA[r & 1], stB[r & 1], wm, wn);
        __syncthreads();
    }
#pragma unroll
    for (int nf = 0; nf < 4; nf++) {
        int col = n0 + wn + nf * 8 + 2 * tig;
        int r0 = m0 + wm + g, r1 = r0 + 8;
        C[(size_t)r0 * Dn + col]     = acc[nf][0];
        C[(size_t)r0 * Dn + col + 1] = acc[nf][1];
        C[(size_t)r1 * Dn + col]     = acc[nf][2];
        C[(size_t)r1 * Dn + col + 1] = acc[nf][3];
    }
}

// ---------------- launch ----------------
extern "C" void kernel_launch(void* const* d_in, const int* in_sizes, int n_in,
                              void* d_out, int out_size) {
    const float* x   = (const float*)d_in[0];
    const float* Wq  = (const float*)d_in[1];
    const float* Wk  = (const float*)d_in[2];
    const float* Wv  = (const float*)d_in[3];
    const float* Wo  = (const float*)d_in[4];
    const float* Ww1 = (const float*)d_in[5];
    const float* Ww2 = (const float*)d_in[6];
    const float* Wb  = (const float*)d_in[7];
    const float* Wf  = (const float*)d_in[8];
    const float* dl  = (const float*)d_in[9];
    float* out = (float*)d_out;

    const int SM_BF = (64 * 128 + 128 * 32) * (int)sizeof(float);

    static float *Ww;
    static bool init = false;
    if (!init) {
        void* p;
        cudaGetSymbolAddress(&p, g_Ww); Ww = (float*)p;
        cudaFuncSetAttribute(proj_kernel,  cudaFuncAttributeMaxDynamicSharedMemorySize, SM_PIPE);
        cudaFuncSetAttribute(solve_kernel, cudaFuncAttributeMaxDynamicSharedMemorySize, SM_PIPE);
        cudaFuncSetAttribute(s_kernel,     cudaFuncAttributeMaxDynamicSharedMemorySize, SM_PIPE);
        cudaFuncSetAttribute(pv_kernel,    cudaFuncAttributeMaxDynamicSharedMemorySize, SM_PIPE);
        cudaFuncSetAttribute(out_kernel,   cudaFuncAttributeMaxDynamicSharedMemorySize, SM_PIPE);
        cudaFuncSetAttribute(tinv_kernel,  cudaFuncAttributeMaxDynamicSharedMemorySize, SM_TINV);
        cudaFuncSetAttribute(l_kernel,     cudaFuncAttributeMaxDynamicSharedMemorySize, SM_ONE);
        cudaFuncSetAttribute(g_kernel,     cudaFuncAttributeMaxDynamicSharedMemorySize, SM_ONE);
        cudaFuncSetAttribute(bf_kernel,    cudaFuncAttributeMaxDynamicSharedMemorySize, SM_BF);
        init = true;
    }

    dim3 thr(256);

    gemm_kernel<<<dim3(16, 16), thr>>>(Ww1, Ww2, Ww, Dn, Dn, HDn);
    bf_kernel<<<dim3(32, 8), thr, SM_BF>>>(x, Wb, Wf);
    gate_kernel<<<32, thr>>>(dl);

    proj_kernel<<<dim3(16, 32, 4), thr, SM_PIPE>>>(x, Wq, Wk, Wv);

    l_kernel<<<dim3(256, 32), thr, SM_ONE>>>();
    tinv_kernel<<<dim3(16, 32), thr, SM_TINV>>>();

    solve_kernel<<<dim3(NBn, BHn), thr, SM_PIPE>>>();   // single launch, column-parallel

    g_kernel<<<dim3(256, 32), thr, SM_ONE>>>();
    s_kernel<<<dim3(256, 32), thr, SM_PIPE>>>();
    softmax_kernel<<<dim3(1024, 32), dim3(128)>>>();
    pv_kernel<<<dim3(16, 32), thr, SM_PIPE>>>();

    out_kernel<<<dim3(16, 32), thr, SM_PIPE>>>(Wo, out);
}